// round 12
// baseline (speedup 1.0000x reference)
#include <cuda_runtime.h>
#include <math.h>

// LatentRNN: B=2048, T=512, P=8, L=64, H=180
// 256 persistent CTAs x 8 batch rows, 544 threads, 2 CTAs/SM.
// Flattened pipeline: gh(t+1) hoisted into D phase, E fused with A,
// 5 barriers/step. Packed transposed weights (coalesced LDG).

#define B_    2048
#define T_    512
#define P_    8
#define L_    64
#define H_    180
#define IN_K  72
#define BT    8
#define NTHR  544
#define GRID  (B_ / BT)

// packed weights
__device__ float4 g_Wc4[180 * 270];   // [k][colgroup4] fused [W_ih | W_hh]
__device__ float  g_Wb1[72 * 180];    // [k][col] W_in
__device__ float2 g_Wd2[244 * 90];    // [k][colpair] W_o1
__device__ float2 g_We2[180 * 32];    // [k][colpair] W_o2
__device__ float2 g_Wh2[64 * 90];     // [k][colpair] W_hp

#define N_C  (180 * 270)
#define N_B1 (72 * 180)
#define N_D  (244 * 90)
#define N_E  (180 * 32)
#define N_H  (64 * 90)

__global__ void prep_kernel(const float* __restrict__ Wih,
                            const float* __restrict__ Whh,
                            const float* __restrict__ Win,
                            const float* __restrict__ Wo1,
                            const float* __restrict__ Wo2,
                            const float* __restrict__ Whp)
{
    int i = blockIdx.x * blockDim.x + threadIdx.x;
    if (i < N_C) {
        int k = i / 270, g = i - k * 270;
        float v[4];
#pragma unroll
        for (int c = 0; c < 4; c++) {
            int j = 4 * g + c;
            v[c] = (j < 540) ? Wih[j * H_ + k] : Whh[(j - 540) * H_ + k];
        }
        g_Wc4[k * 270 + g] = make_float4(v[0], v[1], v[2], v[3]);
        return;
    }
    i -= N_C;
    if (i < N_B1) {
        int k = i / 180, j = i - k * 180;
        g_Wb1[k * 180 + j] = Win[j * IN_K + k];
        return;
    }
    i -= N_B1;
    if (i < N_D) {
        int k = i / 90, c = i - k * 90;
        g_Wd2[k * 90 + c] = make_float2(Wo1[(2*c) * 244 + k], Wo1[(2*c+1) * 244 + k]);
        return;
    }
    i -= N_D;
    if (i < N_E) {
        int k = i / 32, c = i - k * 32;
        g_We2[k * 32 + c] = make_float2(Wo2[(2*c) * H_ + k], Wo2[(2*c+1) * H_ + k]);
        return;
    }
    i -= N_E;
    if (i < N_H) {
        int k = i / 90, c = i - k * 90;
        g_Wh2[k * 90 + c] = make_float2(Whp[(2*c) * L_ + k], Whp[(2*c+1) * L_ + k]);
    }
}

struct __align__(16) Smem {
    float inT [IN_K][BT];      // [phys_t ; cur] transposed (maintained by E/A')
    float xT  [H_][BT];        // gelu(in @ W_in^T)
    float hT  [2][H_][BT];     // hidden state, double buffered
    float oT  [H_][BT];        // gelu(cat @ W_o1^T)
    float giT [540][BT];       // gi (+bias); rows 0..179 overwritten with h_new
    float ghT [540][BT];       // gh (+bias), produced one step ahead
    float catC[L_][BT];        // cur transposed
    float cur [BT][L_];        // current latents, row-major
    float sb  [1684];          // ih 0 | hh 540 | in 1080 | o1 1260 | o2 1440 | hp 1504
};

__device__ __forceinline__ float gelu_f(float v) {
    return 0.5f * v * (1.0f + erff(v * 0.70710678118654752440f));
}
__device__ __forceinline__ float sigmoid_f(float v) {
    return 1.0f / (1.0f + expf(-v));
}

// 2 cols x 4 rows micro-GEMM over [k][LDW]-packed float2 weights.
template<int K, int LDW>
__device__ __forceinline__ void col2x4(const float2* __restrict__ w,
                                       const float* __restrict__ act,
                                       float* __restrict__ acc0,
                                       float* __restrict__ acc1)
{
#pragma unroll 4
    for (int k = 0; k < K; k++) {
        float2 w2 = w[k * LDW];
        float4 a = *(const float4*)(act + k * BT);
        acc0[0] = fmaf(a.x, w2.x, acc0[0]); acc1[0] = fmaf(a.x, w2.y, acc1[0]);
        acc0[1] = fmaf(a.y, w2.x, acc0[1]); acc1[1] = fmaf(a.y, w2.y, acc1[1]);
        acc0[2] = fmaf(a.z, w2.x, acc0[2]); acc1[2] = fmaf(a.z, w2.y, acc1[2]);
        acc0[3] = fmaf(a.w, w2.x, acc0[3]); acc1[3] = fmaf(a.w, w2.y, acc1[3]);
    }
}

// 4 cols x 4 rows over g_Wc4 ([k][270] float4): gcol selects column group.
__device__ __forceinline__ void col4x4_c(int gcol, const float* __restrict__ act,
                                         float acc[4][4])
{
    const float4* wp = g_Wc4 + gcol;
#pragma unroll 4
    for (int k = 0; k < H_; k++) {
        float4 w4 = wp[k * 270];
        float4 a  = *(const float4*)(act + k * BT);
        acc[0][0] = fmaf(a.x, w4.x, acc[0][0]);
        acc[0][1] = fmaf(a.y, w4.x, acc[0][1]);
        acc[0][2] = fmaf(a.z, w4.x, acc[0][2]);
        acc[0][3] = fmaf(a.w, w4.x, acc[0][3]);
        acc[1][0] = fmaf(a.x, w4.y, acc[1][0]);
        acc[1][1] = fmaf(a.y, w4.y, acc[1][1]);
        acc[1][2] = fmaf(a.z, w4.y, acc[1][2]);
        acc[1][3] = fmaf(a.w, w4.y, acc[1][3]);
        acc[2][0] = fmaf(a.x, w4.z, acc[2][0]);
        acc[2][1] = fmaf(a.y, w4.z, acc[2][1]);
        acc[2][2] = fmaf(a.z, w4.z, acc[2][2]);
        acc[2][3] = fmaf(a.w, w4.z, acc[2][3]);
        acc[3][0] = fmaf(a.x, w4.w, acc[3][0]);
        acc[3][1] = fmaf(a.y, w4.w, acc[3][1]);
        acc[3][2] = fmaf(a.z, w4.w, acc[3][2]);
        acc[3][3] = fmaf(a.w, w4.w, acc[3][3]);
    }
}

__global__ __launch_bounds__(NTHR, 2)
void latent_rnn_kernel(const float* __restrict__ phys,
                       const float* __restrict__ latents,
                       const float* __restrict__ b_in,
                       const float* __restrict__ b_hp,
                       const float* __restrict__ b_ih,
                       const float* __restrict__ b_hh,
                       const float* __restrict__ b_o1,
                       const float* __restrict__ b_o2,
                       float* __restrict__ out)
{
    extern __shared__ char smem_raw[];
    Smem* s = reinterpret_cast<Smem*>(smem_raw);
    const int tid = threadIdx.x;
    const int b0  = blockIdx.x * BT;

    // ---- init: cur / catC = latents; biases ----
    for (int i = tid; i < BT * L_; i += NTHR) {
        int r = i >> 6, l = i & 63;
        float v = latents[(b0 + r) * L_ + l];
        s->cur[r][l]  = v;
        s->catC[l][r] = v;
    }
    for (int i = tid; i < 540;  i += NTHR) s->sb[i]        = b_ih[i];
    for (int i = tid; i < 540;  i += NTHR) s->sb[540 + i]  = b_hh[i];
    for (int i = tid; i < 180;  i += NTHR) s->sb[1080 + i] = b_in[i];
    for (int i = tid; i < 180;  i += NTHR) s->sb[1260 + i] = b_o1[i];
    for (int i = tid; i < 64;   i += NTHR) s->sb[1440 + i] = b_o2[i];
    for (int i = tid; i < 180;  i += NTHR) s->sb[1504 + i] = b_hp[i];
    __syncthreads();

    // ---- h0 (tid<180) + inT for t=0 (all threads) ----
    for (int i = tid; i < BT * IN_K; i += NTHR) {
        int r = i / IN_K, k = i - r * IN_K;
        s->inT[k][r] = (k < P_) ? phys[((size_t)(b0 + r) * T_) * P_ + k]
                                : s->cur[r][k - P_];
    }
    if (tid < 180) {
        const int c = tid >> 1, ro = (tid & 1) * 4;
        float acc0[4] = {0,0,0,0}, acc1[4] = {0,0,0,0};
        col2x4<L_, 90>(g_Wh2 + c, &s->catC[0][ro], acc0, acc1);
        const int j0 = 2 * c;
        float bb0 = s->sb[1504 + j0], bb1 = s->sb[1504 + j0 + 1];
#pragma unroll
        for (int i = 0; i < 4; i++) {
            s->hT[0][j0][ro + i]     = acc0[i] + bb0;
            s->hT[0][j0 + 1][ro + i] = acc1[i] + bb1;
        }
    }
    __syncthreads();

    // ---- gh(0) = h0 @ W_hh + b_hh  (270 tasks) ----
    if (tid < 270) {
        const int gcol = 135 + (tid >> 1), ro = (tid & 1) * 4;
        float acc[4][4];
#pragma unroll
        for (int c = 0; c < 4; c++)
#pragma unroll
            for (int i = 0; i < 4; i++) acc[c][i] = 0.f;
        col4x4_c(gcol, &s->hT[0][0][ro], acc);
#pragma unroll
        for (int c = 0; c < 4; c++) {
            const int col = 4 * gcol + c;
            float bb = s->sb[col];
            *(float4*)&s->ghT[col - 540][ro] =
                make_float4(acc[c][0] + bb, acc[c][1] + bb,
                            acc[c][2] + bb, acc[c][3] + bb);
        }
    }
    __syncthreads();

    for (int t = 0; t < T_; t++) {
        const int cb = t & 1, nb = cb ^ 1;

        // ---- P1: B — xT = gelu(inT @ W_in^T + b_in)  (360 n=1 tasks) ----
        if (tid < 360) {
            const int j = tid >> 1, ro = (tid & 1) * 4;
            float acc[4] = {0,0,0,0};
#pragma unroll 4
            for (int k = 0; k < IN_K; k++) {
                float w = g_Wb1[k * 180 + j];
                float4 a = *(const float4*)&s->inT[k][ro];
                acc[0] = fmaf(a.x, w, acc[0]);
                acc[1] = fmaf(a.y, w, acc[1]);
                acc[2] = fmaf(a.z, w, acc[2]);
                acc[3] = fmaf(a.w, w, acc[3]);
            }
            float bb = s->sb[1080 + j];
#pragma unroll
            for (int i = 0; i < 4; i++) s->xT[j][ro + i] = gelu_f(acc[i] + bb);
        }
        __syncthreads();   // (1) xT ready

        // ---- P2: gi = x @ W_ih^T + b_ih  (270 tasks, 4c x 4r) ----
        if (tid < 270) {
            const int gcol = tid >> 1, ro = (tid & 1) * 4;
            float acc[4][4];
#pragma unroll
            for (int c = 0; c < 4; c++)
#pragma unroll
                for (int i = 0; i < 4; i++) acc[c][i] = 0.f;
            col4x4_c(gcol, &s->xT[0][ro], acc);
#pragma unroll
            for (int c = 0; c < 4; c++) {
                const int col = 4 * gcol + c;
                float bb = s->sb[col];
                *(float4*)&s->giT[col][ro] =
                    make_float4(acc[c][0] + bb, acc[c][1] + bb,
                                acc[c][2] + bb, acc[c][3] + bb);
            }
        }
        __syncthreads();   // (2) gi ready (gh ready from prev step)

        // ---- gates: h_new -> hT[nb]; giT[0..179] := h_new ----
        for (int i = tid; i < H_ * BT; i += NTHR) {
            int j = i >> 3, r = i & 7;
            float rg = sigmoid_f(s->giT[j][r]        + s->ghT[j][r]);
            float zg = sigmoid_f(s->giT[j + H_][r]   + s->ghT[j + H_][r]);
            float ng = tanhf    (s->giT[j + 2*H_][r] + rg * s->ghT[j + 2*H_][r]);
            float hn = (1.f - zg) * ng + zg * s->hT[cb][j][r];
            s->hT[nb][j][r] = hn;
            s->giT[j][r] = hn;      // owned element, read-before-write above
        }
        __syncthreads();   // (3) h_new ready, ghT consumed

        // ---- P3: D (tid<180)  ||  gh(t+1) (180<=tid<450) ----
        if (tid < 180) {
            const int c = tid >> 1, ro = (tid & 1) * 4;
            float acc0[4] = {0,0,0,0}, acc1[4] = {0,0,0,0};
            col2x4<H_, 90>(g_Wd2 + c, &s->giT[0][ro], acc0, acc1);             // h_new
            col2x4<L_, 90>(g_Wd2 + 180 * 90 + c, &s->catC[0][ro], acc0, acc1); // cur
            const int j0 = 2 * c;
            float bb0 = s->sb[1260 + j0], bb1 = s->sb[1260 + j0 + 1];
#pragma unroll
            for (int i = 0; i < 4; i++) {
                s->oT[j0][ro + i]     = gelu_f(acc0[i] + bb0);
                s->oT[j0 + 1][ro + i] = gelu_f(acc1[i] + bb1);
            }
        } else if (tid < 450 && t + 1 < T_) {
            const int u = tid - 180;
            const int gcol = 135 + (u >> 1), ro = (u & 1) * 4;
            float acc[4][4];
#pragma unroll
            for (int c = 0; c < 4; c++)
#pragma unroll
                for (int i = 0; i < 4; i++) acc[c][i] = 0.f;
            col4x4_c(gcol, &s->hT[nb][0][ro], acc);
#pragma unroll
            for (int c = 0; c < 4; c++) {
                const int col = 4 * gcol + c;
                float bb = s->sb[col];
                *(float4*)&s->ghT[col - 540][ro] =
                    make_float4(acc[c][0] + bb, acc[c][1] + bb,
                                acc[c][2] + bb, acc[c][3] + bb);
            }
        }
        __syncthreads();   // (4) oT ready; ghT(t+1) ready

        // ---- E + A': cur update, out store, next-step inT/catC ----
        if (tid < 128) {
            const int g = tid >> 2, rq = tid & 3, ro = rq * 2;
            float a0[2] = {0,0}, a1[2] = {0,0};
            const float2* w = g_We2 + g;
#pragma unroll 4
            for (int k = 0; k < H_; k++) {
                float2 w2 = w[k * 32];
                float2 a = *(const float2*)&s->oT[k][ro];
                a0[0] = fmaf(a.x, w2.x, a0[0]); a1[0] = fmaf(a.x, w2.y, a1[0]);
                a0[1] = fmaf(a.y, w2.x, a0[1]); a1[1] = fmaf(a.y, w2.y, a1[1]);
            }
            const int j0 = 2 * g;
            float bb0 = s->sb[1440 + j0], bb1 = s->sb[1440 + j0 + 1];
#pragma unroll
            for (int i = 0; i < 2; i++) {
                int r = ro + i;
                float c0 = fminf(fmaxf(s->cur[r][j0]     + a0[i] + bb0, 0.f), 1.f);
                float c1 = fminf(fmaxf(s->cur[r][j0 + 1] + a1[i] + bb1, 0.f), 1.f);
                s->cur[r][j0]     = c0;
                s->cur[r][j0 + 1] = c1;
                s->catC[j0][r]     = c0;
                s->catC[j0 + 1][r] = c1;
                s->inT[P_ + j0][r]     = c0;
                s->inT[P_ + j0 + 1][r] = c1;
                out[((size_t)(b0 + r) * T_ + t) * L_ + j0]     = c0;
                out[((size_t)(b0 + r) * T_ + t) * L_ + j0 + 1] = c1;
            }
        } else if (tid < 192 && t + 1 < T_) {
            const int u = tid - 128;           // 64 elements: phys(t+1)
            const int k = u >> 3, r = u & 7;
            s->inT[k][r] = phys[((size_t)(b0 + r) * T_ + (t + 1)) * P_ + k];
        }
        __syncthreads();   // (5) cur/inT/catC ready for next step
    }
}

extern "C" void kernel_launch(void* const* d_in, const int* in_sizes, int n_in,
                              void* d_out, int out_size)
{
    const float* phys    = (const float*)d_in[0];
    const float* latents = (const float*)d_in[1];
    const float* W_in    = (const float*)d_in[2];
    const float* b_in    = (const float*)d_in[3];
    const float* W_hp    = (const float*)d_in[4];
    const float* b_hp    = (const float*)d_in[5];
    const float* W_ih    = (const float*)d_in[6];
    const float* b_ih    = (const float*)d_in[7];
    const float* W_hh    = (const float*)d_in[8];
    const float* b_hh    = (const float*)d_in[9];
    const float* W_o1    = (const float*)d_in[10];
    const float* b_o1    = (const float*)d_in[11];
    const float* W_o2    = (const float*)d_in[12];
    const float* b_o2    = (const float*)d_in[13];
    float* out = (float*)d_out;

    static bool attr_set = false;
    if (!attr_set) {
        cudaFuncSetAttribute(latent_rnn_kernel,
                             cudaFuncAttributeMaxDynamicSharedMemorySize,
                             (int)sizeof(Smem));
        attr_set = true;
    }

    prep_kernel<<<(N_C + N_B1 + N_D + N_E + N_H + 255) / 256, 256>>>(
        W_ih, W_hh, W_in, W_o1, W_o2, W_hp);

    latent_rnn_kernel<<<GRID, NTHR, sizeof(Smem)>>>(
        phys, latents, b_in, b_hp, b_ih, b_hh, b_o1, b_o2, out);
}

// round 13
// speedup vs baseline: 1.6314x; 1.6314x over previous
#include <cuda_runtime.h>
#include <math.h>

// LatentRNN: B=2048, T=512, P=8, L=64, H=180
// 128 persistent CTAs x 16 batch rows, 640 threads (R6 base).
// Phase C retiled: n=2 cols x m=16 rows, [k/2][540]-packed float4 weights
// (one coalesced LDG.128 per 2 cols x 2 k), single pass, PF=2 weight ring.

#define B_    2048
#define T_    512
#define P_    8
#define L_    64
#define H_    180
#define IN_K  72
#define BT    16
#define NTHR  640
#define GST   20          // padded row stride for giT/ghT

// packed weights
__device__ float4 g_Wc4[90 * 540];    // [k2][colpair] fused [W_ih|W_hh]:
                                      // {w(j0,2k2), w(j1,2k2), w(j0,2k2+1), w(j1,2k2+1)}
__device__ float4 g_Wb4[18 * 180];    // [kq][col] W_in, K=72
__device__ float4 g_Wd4[61 * 180];    // [kq][col] W_o1, K=244
__device__ float4 g_We4[45 * 64];     // [kq][col] W_o2, K=180
__device__ float4 g_Wh4[16 * 180];    // [kq][col] W_hp, K=64

#define N_C (90 * 540)
#define N_B (18 * 180)
#define N_D (61 * 180)
#define N_E (45 * 64)
#define N_H (16 * 180)

__global__ void prep_kernel(const float* __restrict__ Wih,
                            const float* __restrict__ Whh,
                            const float* __restrict__ Win,
                            const float* __restrict__ Wo1,
                            const float* __restrict__ Wo2,
                            const float* __restrict__ Whp)
{
    int i = blockIdx.x * blockDim.x + threadIdx.x;
    if (i < N_C) {
        int k2 = i / 540, p = i - k2 * 540;
        int j0 = 2 * p, j1 = j0 + 1;
        int k0 = 2 * k2, k1 = k0 + 1;
        float x = (j0 < 540) ? Wih[j0 * H_ + k0] : Whh[(j0 - 540) * H_ + k0];
        float y = (j1 < 540) ? Wih[j1 * H_ + k0] : Whh[(j1 - 540) * H_ + k0];
        float z = (j0 < 540) ? Wih[j0 * H_ + k1] : Whh[(j0 - 540) * H_ + k1];
        float w = (j1 < 540) ? Wih[j1 * H_ + k1] : Whh[(j1 - 540) * H_ + k1];
        g_Wc4[k2 * 540 + p] = make_float4(x, y, z, w);
        return;
    }
    i -= N_C;
    if (i < N_B) {
        int kq = i / 180, j = i - kq * 180;
        g_Wb4[kq * 180 + j] = *(const float4*)(Win + j * IN_K + kq * 4);
        return;
    }
    i -= N_B;
    if (i < N_D) {
        int kq = i / 180, j = i - kq * 180;
        g_Wd4[kq * 180 + j] = *(const float4*)(Wo1 + j * 244 + kq * 4);
        return;
    }
    i -= N_D;
    if (i < N_E) {
        int kq = i / 64, j = i - kq * 64;
        g_We4[kq * 64 + j] = *(const float4*)(Wo2 + j * H_ + kq * 4);
        return;
    }
    i -= N_E;
    if (i < N_H) {
        int kq = i / 180, j = i - kq * 180;
        g_Wh4[kq * 180 + j] = *(const float4*)(Whp + j * L_ + kq * 4);
    }
}

struct __align__(16) Smem {
    float inT[IN_K][BT];       // [phys_t ; cur] transposed
    float xT [H_][BT];         // gelu(in @ W_in^T)
    float hT [2][H_][BT];      // hidden state, double buffered
    float oT [H_][BT];         // gelu(cat @ W_o1^T)
    float giT[540][GST];       // gi (+bias); rows 0..179 -> h_new, 180..243 -> cur
    float ghT[540][GST];       // gh (+bias)
    float cur[BT][L_];         // current latents, row-major
    float sb [1684];           // ih 0 | hh 540 | in 1080 | o1 1260 | o2 1440 | hp 1504
};

__device__ __forceinline__ float gelu_f(float v) {
    return 0.5f * v * (1.0f + erff(v * 0.70710678118654752440f));
}
__device__ __forceinline__ float sigmoid_f(float v) {
    return 1.0f / (1.0f + expf(-v));
}

// R6 column GEMM: NR rows, K = 4*NKQ, weight float4 at w[kq*STRIDE].
template<int NR, int NKQ, int STRIDE, int LDA>
__device__ __forceinline__ void pcol(const float4* __restrict__ w,
                                     const float* __restrict__ act,
                                     float* __restrict__ acc)
{
#pragma unroll 3
    for (int kq = 0; kq < NKQ; kq++) {
        float4 w4 = w[kq * STRIDE];
        const float* b = act + kq * 4 * LDA;
        float wk[4] = {w4.x, w4.y, w4.z, w4.w};
#pragma unroll
        for (int kk = 0; kk < 4; kk++) {
#pragma unroll
            for (int rq = 0; rq < NR / 4; rq++) {
                float4 a = *(const float4*)(b + kk * LDA + rq * 4);
                acc[rq*4+0] = fmaf(a.x, wk[kk], acc[rq*4+0]);
                acc[rq*4+1] = fmaf(a.y, wk[kk], acc[rq*4+1]);
                acc[rq*4+2] = fmaf(a.z, wk[kk], acc[rq*4+2]);
                acc[rq*4+3] = fmaf(a.w, wk[kk], acc[rq*4+3]);
            }
        }
    }
}

// 16 rows x 2 cols FMA for one k: shared act loads feed both accumulators.
__device__ __forceinline__ void fma2x16(float* __restrict__ acc0,
                                        float* __restrict__ acc1,
                                        const float* __restrict__ ap,
                                        float wx, float wy)
{
    float4 a0 = *(const float4*)(ap);
    float4 a1 = *(const float4*)(ap + 4);
    float4 a2 = *(const float4*)(ap + 8);
    float4 a3 = *(const float4*)(ap + 12);
    acc0[0]  = fmaf(a0.x, wx, acc0[0]);  acc1[0]  = fmaf(a0.x, wy, acc1[0]);
    acc0[1]  = fmaf(a0.y, wx, acc0[1]);  acc1[1]  = fmaf(a0.y, wy, acc1[1]);
    acc0[2]  = fmaf(a0.z, wx, acc0[2]);  acc1[2]  = fmaf(a0.z, wy, acc1[2]);
    acc0[3]  = fmaf(a0.w, wx, acc0[3]);  acc1[3]  = fmaf(a0.w, wy, acc1[3]);
    acc0[4]  = fmaf(a1.x, wx, acc0[4]);  acc1[4]  = fmaf(a1.x, wy, acc1[4]);
    acc0[5]  = fmaf(a1.y, wx, acc0[5]);  acc1[5]  = fmaf(a1.y, wy, acc1[5]);
    acc0[6]  = fmaf(a1.z, wx, acc0[6]);  acc1[6]  = fmaf(a1.z, wy, acc1[6]);
    acc0[7]  = fmaf(a1.w, wx, acc0[7]);  acc1[7]  = fmaf(a1.w, wy, acc1[7]);
    acc0[8]  = fmaf(a2.x, wx, acc0[8]);  acc1[8]  = fmaf(a2.x, wy, acc1[8]);
    acc0[9]  = fmaf(a2.y, wx, acc0[9]);  acc1[9]  = fmaf(a2.y, wy, acc1[9]);
    acc0[10] = fmaf(a2.z, wx, acc0[10]); acc1[10] = fmaf(a2.z, wy, acc1[10]);
    acc0[11] = fmaf(a2.w, wx, acc0[11]); acc1[11] = fmaf(a2.w, wy, acc1[11]);
    acc0[12] = fmaf(a3.x, wx, acc0[12]); acc1[12] = fmaf(a3.x, wy, acc1[12]);
    acc0[13] = fmaf(a3.y, wx, acc0[13]); acc1[13] = fmaf(a3.y, wy, acc1[13]);
    acc0[14] = fmaf(a3.z, wx, acc0[14]); acc1[14] = fmaf(a3.z, wy, acc1[14]);
    acc0[15] = fmaf(a3.w, wx, acc0[15]); acc1[15] = fmaf(a3.w, wy, acc1[15]);
}

__global__ __launch_bounds__(NTHR, 1)
void latent_rnn_kernel(const float* __restrict__ phys,
                       const float* __restrict__ latents,
                       const float* __restrict__ b_in,
                       const float* __restrict__ b_hp,
                       const float* __restrict__ b_ih,
                       const float* __restrict__ b_hh,
                       const float* __restrict__ b_o1,
                       const float* __restrict__ b_o2,
                       float* __restrict__ out)
{
    extern __shared__ char smem_raw[];
    Smem* s = reinterpret_cast<Smem*>(smem_raw);
    const int tid = threadIdx.x;
    const int b0  = blockIdx.x * BT;

    // ---- init: cur = latents; latents^T into inT; biases ----
    for (int i = tid; i < BT * L_; i += NTHR) {
        int r = i >> 6, l = i & 63;
        float v = latents[(b0 + r) * L_ + l];
        s->cur[r][l] = v;
        s->inT[l][r] = v;
    }
    for (int i = tid; i < 540;  i += NTHR) s->sb[i]        = b_ih[i];
    for (int i = tid; i < 540;  i += NTHR) s->sb[540 + i]  = b_hh[i];
    for (int i = tid; i < 180;  i += NTHR) s->sb[1080 + i] = b_in[i];
    for (int i = tid; i < 180;  i += NTHR) s->sb[1260 + i] = b_o1[i];
    for (int i = tid; i < 64;   i += NTHR) s->sb[1440 + i] = b_o2[i];
    for (int i = tid; i < 180;  i += NTHR) s->sb[1504 + i] = b_hp[i];
    __syncthreads();

    // ---- h0 = latents @ W_hp^T + b_hp ----
    if (tid < 360) {
        int j = tid >> 1, ro = (tid & 1) * 8;
        float acc[8] = {0,0,0,0,0,0,0,0};
        pcol<8, 16, 180, BT>(g_Wh4 + j, &s->inT[0][ro], acc);
        float bb = s->sb[1504 + j];
#pragma unroll
        for (int i = 0; i < 8; i++) s->hT[0][j][ro + i] = acc[i] + bb;
    }

    for (int t = 0; t < T_; t++) {
        const int cb = t & 1, nb = cb ^ 1;
        __syncthreads();   // (0) prev-E cur / h0 ready

        // ---- A: inT = [phys_t ; cur] transposed ----
        for (int i = tid; i < BT * IN_K; i += NTHR) {
            int r = i / IN_K, k = i - r * IN_K;
            s->inT[k][r] = (k < P_) ? phys[((size_t)(b0 + r) * T_ + t) * P_ + k]
                                    : s->cur[r][k - P_];
        }
        __syncthreads();   // (1) inT ready

        // ---- B: xT = gelu(inT @ W_in^T + b_in) ----
        if (tid < 360) {
            int j = tid >> 1, ro = (tid & 1) * 8;
            float acc[8] = {0,0,0,0,0,0,0,0};
            pcol<8, 18, 180, BT>(g_Wb4 + j, &s->inT[0][ro], acc);
            float bb = s->sb[1080 + j];
#pragma unroll
            for (int i = 0; i < 8; i++) s->xT[j][ro + i] = gelu_f(acc[i] + bb);
        }
        __syncthreads();   // (2) xT ready

        // ---- C: gi/gh, single pass. Task p owns cols {2p, 2p+1} x 16 rows.
        //      One LDG.128 per 2 cols x 2 k; act LDS shared by both cols;
        //      PF=2 weight prefetch ring. ----
        if (tid < 540) {
            const int p = tid;
            const bool gh = (p >= 270);         // cols >= 540
            const float* act = gh ? &s->hT[cb][0][0] : &s->xT[0][0];
            const float4* wp = g_Wc4 + p;
            float acc0[16], acc1[16];
#pragma unroll
            for (int i = 0; i < 16; i++) { acc0[i] = 0.f; acc1[i] = 0.f; }
            float4 wc = wp[0];
            float4 wn = wp[540];
#pragma unroll 3
            for (int k2 = 0; k2 < 90; k2++) {
                float4 w = wc;
                wc = wn;
                int kpf = (k2 + 2 < 90) ? (k2 + 2) : 89;
                wn = wp[kpf * 540];
                const float* ap = act + (2 * k2) * BT;
                fma2x16(acc0, acc1, ap,      w.x, w.y);   // k = 2k2
                fma2x16(acc0, acc1, ap + BT, w.z, w.w);   // k = 2k2+1
            }
            const int j0 = 2 * p;
            float bb0 = s->sb[j0], bb1 = s->sb[j0 + 1];
            float* d0 = gh ? s->ghT[j0 - 540] : s->giT[j0];
            float* d1 = gh ? s->ghT[j0 - 539] : s->giT[j0 + 1];
#pragma unroll
            for (int rq = 0; rq < 4; rq++) {
                *(float4*)(d0 + rq * 4) =
                    make_float4(acc0[rq*4+0] + bb0, acc0[rq*4+1] + bb0,
                                acc0[rq*4+2] + bb0, acc0[rq*4+3] + bb0);
                *(float4*)(d1 + rq * 4) =
                    make_float4(acc1[rq*4+0] + bb1, acc1[rq*4+1] + bb1,
                                acc1[rq*4+2] + bb1, acc1[rq*4+3] + bb1);
            }
        }
        __syncthreads();   // (3) gi/gh ready

        // ---- gates: h_new -> hT[nb]; giT[0..179] := h_new ----
        for (int i = tid; i < H_ * BT; i += NTHR) {
            int j = i >> 4, r = i & 15;
            float rg = sigmoid_f(s->giT[j][r]        + s->ghT[j][r]);
            float zg = sigmoid_f(s->giT[j + H_][r]   + s->ghT[j + H_][r]);
            float ng = tanhf    (s->giT[j + 2*H_][r] + rg * s->ghT[j + 2*H_][r]);
            float hn = (1.f - zg) * ng + zg * s->hT[cb][j][r];
            s->hT[nb][j][r] = hn;
            s->giT[j][r] = hn;      // owned element, read-before-write above
        }
        __syncthreads();   // (4) all gate reads done

        // ---- catT rows 180..243 = cur (transposed) ----
        for (int i = tid; i < L_ * BT; i += NTHR) {
            int l = i >> 4, r = i & 15;
            s->giT[H_ + l][r] = s->cur[r][l];
        }
        __syncthreads();   // (5) cat ready

        // ---- D: oT = gelu([h_new ; cur] @ W_o1^T + b_o1) ----
        if (tid < 360) {
            int j = tid >> 1, ro = (tid & 1) * 8;
            float acc[8] = {0,0,0,0,0,0,0,0};
            pcol<8, 61, 180, GST>(g_Wd4 + j, &s->giT[0][ro], acc);
            float bb = s->sb[1260 + j];
#pragma unroll
            for (int i = 0; i < 8; i++) s->oT[j][ro + i] = gelu_f(acc[i] + bb);
        }
        __syncthreads();   // (6) oT ready

        // ---- E: delta = oT @ W_o2^T + b_o2; cur = clip(cur + delta); store ----
        if (tid < 256) {
            int j = tid >> 2, ro = (tid & 3) * 4;
            float acc[4] = {0,0,0,0};
            pcol<4, 45, 64, BT>(g_We4 + j, &s->oT[0][ro], acc);
            float bb = s->sb[1440 + j];
#pragma unroll
            for (int i = 0; i < 4; i++) {
                int r = ro + i;
                float c = fminf(fmaxf(s->cur[r][j] + acc[i] + bb, 0.f), 1.f);
                s->cur[r][j] = c;
                out[((size_t)(b0 + r) * T_ + t) * L_ + j] = c;
            }
        }
    }
}

extern "C" void kernel_launch(void* const* d_in, const int* in_sizes, int n_in,
                              void* d_out, int out_size)
{
    const float* phys    = (const float*)d_in[0];
    const float* latents = (const float*)d_in[1];
    const float* W_in    = (const float*)d_in[2];
    const float* b_in    = (const float*)d_in[3];
    const float* W_hp    = (const float*)d_in[4];
    const float* b_hp    = (const float*)d_in[5];
    const float* W_ih    = (const float*)d_in[6];
    const float* b_ih    = (const float*)d_in[7];
    const float* W_hh    = (const float*)d_in[8];
    const float* b_hh    = (const float*)d_in[9];
    const float* W_o1    = (const float*)d_in[10];
    const float* b_o1    = (const float*)d_in[11];
    const float* W_o2    = (const float*)d_in[12];
    const float* b_o2    = (const float*)d_in[13];
    float* out = (float*)d_out;

    static bool attr_set = false;
    if (!attr_set) {
        cudaFuncSetAttribute(latent_rnn_kernel,
                             cudaFuncAttributeMaxDynamicSharedMemorySize,
                             (int)sizeof(Smem));
        attr_set = true;
    }

    prep_kernel<<<(N_C + N_B + N_D + N_E + N_H + 255) / 256, 256>>>(
        W_ih, W_hh, W_in, W_o1, W_o2, W_hp);

    latent_rnn_kernel<<<B_ / BT, NTHR, sizeof(Smem)>>>(
        phys, latents, b_in, b_hp, b_ih, b_hh, b_o1, b_o2, out);
}